// round 10
// baseline (speedup 1.0000x reference)
#include <cuda_runtime.h>
#include <cuda_bf16.h>

// Problem constants (from reference setup_inputs)
#define IN_F  512
#define HID   64
#define OUTF  7
#define MAXN  50000
#define MAXE  1600000

// ---------------- scratch (device globals; no allocation allowed) -----------
__device__ __align__(16) int   g_deg[MAXN];     // degree incl. self loop
__device__ __align__(16) float g_dinv[MAXN];
__device__ __align__(16) int   g_off[MAXN];     // CSR row start (by dst)
__device__ __align__(16) int   g_cur[MAXN];     // scatter cursor
__device__ __align__(16) int   g_csrc[MAXE];    // CSR: src per slot
__device__ __align__(16) float g_cnrm[MAXE];    // CSR: norm per slot
__device__ __align__(16) float g_h[MAXN * HID]; // x @ W1
__device__ __align__(16) float g_h2[MAXN * 8];  // layer2 features, padded to 8
__device__ int g_is32;
__device__ int g_total;                         // CSR range allocator cursor

// ---------------- init: deg=1, allocator reset, edge-dtype detect -----------
// Block 0 additionally scans the first 2048 words of the edge buffer: real
// int64 entries are all in [0, N); int32 data misread as int64 produces
// values >= 2^32 (or negative) almost surely.
__global__ void k_init(const long long* __restrict__ ei, int E, int N) {
    int i = blockIdx.x * blockDim.x + threadIdx.x;
    if (i < N) g_deg[i] = 1;
    if (i == 0) g_total = 0;
    if (blockIdx.x == 0) {
        if (threadIdx.x == 0) g_is32 = 0;
        __syncthreads();
        int cnt = min(2 * E, 2048);
        int bad = 0;
        for (int k = threadIdx.x; k < cnt; k += blockDim.x) {
            long long v = ei[k];
            if (v < 0 || v >= (long long)N) bad = 1;
        }
        if (bad) atomicExch(&g_is32, 1);
    }
}

// degree histogram (reads edge dst only)
__global__ void k_deg(const void* __restrict__ eiv, int E) {
    int e = blockIdx.x * blockDim.x + threadIdx.x;
    if (e >= E) return;
    int d;
    if (g_is32) d = ((const int*)eiv)[E + e];
    else        d = (int)((const long long*)eiv)[E + e];
    atomicAdd(&g_deg[d], 1);
}

// CSR range allocation without an ordered scan: warp-aggregated atomic.
// Ranges are contiguous & disjoint (consumers only need off+cnt). dinv fused.
__global__ void k_offsets(int N) {
    int n = blockIdx.x * blockDim.x + threadIdx.x;
    int lane = threadIdx.x & 31;
    int deg = (n < N) ? g_deg[n] : 1;
    int e = deg - 1;
    int x = e;
    #pragma unroll
    for (int off = 1; off < 32; off <<= 1) {
        int y = __shfl_up_sync(0xFFFFFFFFu, x, off);
        if (lane >= off) x += y;
    }
    int warpsum = __shfl_sync(0xFFFFFFFFu, x, 31);
    int base = 0;
    if (lane == 31) base = atomicAdd(&g_total, warpsum);
    base = __shfl_sync(0xFFFFFFFFu, base, 31);
    if (n < N) {
        int off = base + x - e;
        g_off[n] = off;
        g_cur[n] = off;
        g_dinv[n] = rsqrtf((float)deg);
    }
}

// bin edges by dst, reading the edge list directly (still L2-warm)
__global__ void k_scatter(const void* __restrict__ eiv, int E) {
    int e = blockIdx.x * blockDim.x + threadIdx.x;
    if (e >= E) return;
    int s, d;
    if (g_is32) {
        const int* ei = (const int*)eiv;
        s = ei[e]; d = ei[E + e];
    } else {
        const long long* ei = (const long long*)eiv;
        s = (int)ei[e]; d = (int)ei[E + e];
    }
    float nm = g_dinv[s] * g_dinv[d];
    int slot = atomicAdd(&g_cur[d], 1);
    g_csrc[slot] = s;
    g_cnrm[slot] = nm;
}

// ---------------- GEMM1: h = x @ W1  (N x 512 @ 512 x 64) -------------------
// 64x64 tile per block, BK=32, 256 threads, 4x4 accum per thread.
// xs padded to 36 cols: row stride 144B (16B aligned for float4 stores) and
// the two A-rows a warp touches per column land on different banks.
__global__ __launch_bounds__(256) void k_gemm1(const float* __restrict__ x,
                                               const float* __restrict__ W1,
                                               int N) {
    __shared__ float xs[64][36];
    __shared__ float ws[32][64];
    int tid = threadIdx.x;
    int tx = tid & 15, ty = tid >> 4;
    int row0 = blockIdx.x * 64;
    float acc[4][4] = {};

    for (int k0 = 0; k0 < IN_F; k0 += 32) {
        #pragma unroll
        for (int i = 0; i < 2; i++) {
            int f = tid * 2 + i;
            int r = f >> 3, c4 = (f & 7) * 4;
            int gr = row0 + r;
            float4 v = make_float4(0.f, 0.f, 0.f, 0.f);
            if (gr < N) v = *(const float4*)&x[(size_t)gr * IN_F + k0 + c4];
            *(float4*)&xs[r][c4] = v;
        }
        #pragma unroll
        for (int i = 0; i < 2; i++) {
            int f = tid * 2 + i;
            int r = f >> 4, c4 = (f & 15) * 4;
            *(float4*)&ws[r][c4] = *(const float4*)&W1[(k0 + r) * HID + c4];
        }
        __syncthreads();
        #pragma unroll
        for (int k = 0; k < 32; k++) {
            float a[4];
            #pragma unroll
            for (int i = 0; i < 4; i++) a[i] = xs[ty * 4 + i][k];
            float4 bv = *(float4*)&ws[k][tx * 4];
            float b[4] = {bv.x, bv.y, bv.z, bv.w};
            #pragma unroll
            for (int i = 0; i < 4; i++)
                #pragma unroll
                for (int j = 0; j < 4; j++) acc[i][j] += a[i] * b[j];
        }
        __syncthreads();
    }
    #pragma unroll
    for (int i = 0; i < 4; i++) {
        int gr = row0 + ty * 4 + i;
        if (gr < N)
            *(float4*)&g_h[(size_t)gr * HID + tx * 4] =
                make_float4(acc[i][0], acc[i][1], acc[i][2], acc[i][3]);
    }
}

// ---------------- fused layer-1 aggregation + layer-2 transform --------------
// Warp per node; 8 lanes per edge, 4 edges in flight per warp.
// Lane (g = lane/8, p = lane%8) accumulates features [8p, 8p+8) over edges
// {g, g+4, g+8, ...} with two LDG.128 per edge-slice; src/norm come from
// 8-lane same-address loads (L1 broadcast). Cross-group butterfly merges the
// 4 partials, then h2[n] = relu(acc + b1) @ W2 via intra-group reduction.
__global__ __launch_bounds__(256) void k_agg1(const float* __restrict__ b1,
                                              const float* __restrict__ W2,
                                              int N) {
    __shared__ float w2s[HID * OUTF];
    __shared__ float b1s[HID];
    int tid = threadIdx.x;
    for (int i = tid; i < HID * OUTF; i += 256) w2s[i] = W2[i];
    if (tid < HID) b1s[tid] = b1[tid];
    __syncthreads();

    int n = blockIdx.x * 8 + (tid >> 5);
    if (n >= N) return;
    int lane = tid & 31;
    int g = lane >> 3;        // edge group 0..3
    int p = lane & 7;         // feature slice 0..7

    float acc[8] = {};
    int beg = g_off[n];
    int cnt = g_deg[n] - 1;

    #pragma unroll 2
    for (int c = g; c < cnt; c += 4) {
        int   src = g_csrc[beg + c];
        float nm  = g_cnrm[beg + c];
        const float* hp = &g_h[(size_t)src * HID + p * 8];
        float4 v0 = *(const float4*)hp;
        float4 v1 = *(const float4*)(hp + 4);
        acc[0] += v0.x * nm; acc[1] += v0.y * nm;
        acc[2] += v0.z * nm; acc[3] += v0.w * nm;
        acc[4] += v1.x * nm; acc[5] += v1.y * nm;
        acc[6] += v1.z * nm; acc[7] += v1.w * nm;
    }

    // merge the 4 edge-groups (feature slices are disjoint across p, shared across g)
    #pragma unroll
    for (int i = 0; i < 8; i++) acc[i] += __shfl_xor_sync(0xFFFFFFFFu, acc[i], 8);
    #pragma unroll
    for (int i = 0; i < 8; i++) acc[i] += __shfl_xor_sync(0xFFFFFFFFu, acc[i], 16);

    // self loop (after merge: every lane adds once to its consistent copy)
    float di = g_dinv[n];
    float self = di * di;
    {
        const float* hp = &g_h[(size_t)n * HID + p * 8];
        float4 v0 = *(const float4*)hp;
        float4 v1 = *(const float4*)(hp + 4);
        acc[0] += v0.x * self; acc[1] += v0.y * self;
        acc[2] += v0.z * self; acc[3] += v0.w * self;
        acc[4] += v1.x * self; acc[5] += v1.y * self;
        acc[6] += v1.z * self; acc[7] += v1.w * self;
    }

    // relu(acc + b1) @ W2: partials over this lane's 8 features
    float o_[OUTF] = {};
    #pragma unroll
    for (int i = 0; i < 8; i++) {
        int f = p * 8 + i;
        float a = fmaxf(acc[i] + b1s[f], 0.f);
        #pragma unroll
        for (int o = 0; o < OUTF; o++) o_[o] += a * w2s[f * OUTF + o];
    }
    // reduce across the 8 feature slices within one group (groups identical)
    #pragma unroll
    for (int off = 4; off > 0; off >>= 1)
        #pragma unroll
        for (int o = 0; o < OUTF; o++)
            o_[o] += __shfl_down_sync(0xFFFFFFFFu, o_[o], off, 8);

    if (lane == 0) {
        #pragma unroll
        for (int o = 0; o < OUTF; o++) g_h2[n * 8 + o] = o_[o];
        g_h2[n * 8 + 7] = 0.f;
    }
}

// ---------------- fused layer-2 aggregation + bias + output ------------------
// Thread per node.
__global__ void k_agg2(const float* __restrict__ b2, float* __restrict__ out, int N) {
    int n = blockIdx.x * blockDim.x + threadIdx.x;
    if (n >= N) return;
    float di = g_dinv[n];
    float s = di * di;
    float4 lo = *(const float4*)&g_h2[n * 8];
    float4 hi = *(const float4*)&g_h2[n * 8 + 4];
    float a[OUTF] = {lo.x * s, lo.y * s, lo.z * s, lo.w * s,
                     hi.x * s, hi.y * s, hi.z * s};
    int beg = g_off[n];
    int cnt = g_deg[n] - 1;
    #pragma unroll 2
    for (int i = 0; i < cnt; i++) {
        int src = g_csrc[beg + i];
        float nm = g_cnrm[beg + i];
        float4 v = *(const float4*)&g_h2[src * 8];
        float4 w = *(const float4*)&g_h2[src * 8 + 4];
        a[0] += v.x * nm; a[1] += v.y * nm; a[2] += v.z * nm; a[3] += v.w * nm;
        a[4] += w.x * nm; a[5] += w.y * nm; a[6] += w.z * nm;
    }
    #pragma unroll
    for (int o = 0; o < OUTF; o++) out[n * OUTF + o] = a[o] + b2[o];
}

// ---------------- launch -----------------------------------------------------
extern "C" void kernel_launch(void* const* d_in, const int* in_sizes, int n_in,
                              void* d_out, int out_size) {
    const float* x  = (const float*)d_in[0];
    const void*  ei = d_in[1];
    const float* W1 = (const float*)d_in[2];
    const float* b1 = (const float*)d_in[3];
    const float* W2 = (const float*)d_in[4];
    const float* b2 = (const float*)d_in[5];
    float* out = (float*)d_out;

    int N = in_sizes[0] / IN_F;
    int E = in_sizes[1] / 2;

    const int T = 256;
    k_init<<<(N + T - 1) / T, T>>>((const long long*)ei, E, N);
    k_deg<<<(E + T - 1) / T, T>>>(ei, E);
    k_offsets<<<(N + T - 1) / T, T>>>(N);
    k_scatter<<<(E + T - 1) / T, T>>>(ei, E);

    k_gemm1<<<(N + 63) / 64, T>>>(x, W1, N);
    k_agg1<<<(N + 7) / 8, T>>>(b1, W2, N);
    k_agg2<<<(N + T - 1) / T, T>>>(b2, out, N);
}